// round 8
// baseline (speedup 1.0000x reference)
#include <cuda_runtime.h>
#include <cstdint>

// LTC scan, round 8.
// R7 post-mortem: skew neutral; true binder is warp-level latency hiding
// (2 warps/SMSP can't cover BAR+LDS+tanh tails; ~990cyc/unfold vs ~400 floor).
// R8: 512 threads/CTA (grid 128, 4 rows/CTA): thread = (j-pair, k-QUARTER,
// row-pair) -> W regs/thread halved (64), warps/SMSP 2->4, same per-SM work.
// Each thread owns exactly ONE h state. Dot reads remain all-lane broadcast
// LDS.128 (1 wavefront); each 16B h-load still feeds 4 FFMA2.

#define Bsz 512
#define Ssz 512
#define Dsz 128
#define Hsz 128
#define UNFOLDS 6

typedef unsigned long long ull;

__device__ float g_xin[(size_t)Bsz * Ssz * Hsz];   // [b][s][h] scratch

__device__ __forceinline__ ull ffma2(ull a, ull b, ull c) {
    ull d;
    asm("fma.rn.f32x2 %0, %1, %2, %3;" : "=l"(d) : "l"(a), "l"(b), "l"(c));
    return d;
}

__device__ __forceinline__ float f2sum(ull v) {
    float lo, hi;
    asm("mov.b64 {%0, %1}, %2;" : "=f"(lo), "=f"(hi) : "l"(v));
    return lo + hi;
}

__device__ __forceinline__ float ftanh(float s) {
    float e = __expf(2.0f * s);
    return 1.0f - __fdividef(2.0f, e + 1.0f);
}

// ---------------------------------------------------------------------------
// Kernel 1: xin[b,s,j] = sum_d x[b,s,d] * W_in[j,d] + b_in[j]
// ---------------------------------------------------------------------------
__global__ void __launch_bounds__(128, 2)
xin_kernel(const float* __restrict__ x,
           const float* __restrict__ W_in,
           const float* __restrict__ b_in)
{
    __shared__ float xs[2][4 * Dsz];

    const int j = threadIdx.x;

    ull wi[64];
    {
        const ulonglong2* wp = (const ulonglong2*)(W_in + j * Dsz);
        #pragma unroll
        for (int c = 0; c < 32; ++c) {
            ulonglong2 v = wp[c];
            wi[2 * c]     = v.x;
            wi[2 * c + 1] = v.y;
        }
    }
    const float bi = b_in[j];

    const int m0 = blockIdx.x * 128;

    float xf[4];
    #pragma unroll
    for (int r = 0; r < 4; ++r)
        xf[r] = x[(size_t)(m0 + r) * Dsz + j];

    #pragma unroll 1
    for (int ch = 0; ch < 32; ++ch) {
        float* xb = xs[ch & 1];
        #pragma unroll
        for (int r = 0; r < 4; ++r)
            xb[r * Dsz + j] = xf[r];
        __syncthreads();

        if (ch < 31) {
            #pragma unroll
            for (int r = 0; r < 4; ++r)
                xf[r] = x[(size_t)(m0 + (ch + 1) * 4 + r) * Dsz + j];
        }

        ull a0 = 0ull, a1 = 0ull, a2 = 0ull, a3 = 0ull;
        ull a4 = 0ull, a5 = 0ull, a6 = 0ull, a7 = 0ull;
        #pragma unroll
        for (int c = 0; c < 32; ++c) {
            ulonglong2 v0 = *(const ulonglong2*)(xb + 0 * Dsz + 4 * c);
            ulonglong2 v1 = *(const ulonglong2*)(xb + 1 * Dsz + 4 * c);
            ulonglong2 v2 = *(const ulonglong2*)(xb + 2 * Dsz + 4 * c);
            ulonglong2 v3 = *(const ulonglong2*)(xb + 3 * Dsz + 4 * c);
            a0 = ffma2(wi[2 * c], v0.x, a0);  a1 = ffma2(wi[2 * c + 1], v0.y, a1);
            a2 = ffma2(wi[2 * c], v1.x, a2);  a3 = ffma2(wi[2 * c + 1], v1.y, a3);
            a4 = ffma2(wi[2 * c], v2.x, a4);  a5 = ffma2(wi[2 * c + 1], v2.y, a5);
            a6 = ffma2(wi[2 * c], v3.x, a6);  a7 = ffma2(wi[2 * c + 1], v3.y, a7);
        }
        const int m = m0 + ch * 4;
        g_xin[(size_t)(m + 0) * Hsz + j] = f2sum(a0) + f2sum(a1) + bi;
        g_xin[(size_t)(m + 1) * Hsz + j] = f2sum(a2) + f2sum(a3) + bi;
        g_xin[(size_t)(m + 2) * Hsz + j] = f2sum(a4) + f2sum(a5) + bi;
        g_xin[(size_t)(m + 3) * Hsz + j] = f2sum(a6) + f2sum(a7) + bi;
    }
}

// ---------------------------------------------------------------------------
// Kernel 2: sequential scan. grid 128 x 512 threads, 4 rows/CTA.
// Dot identity:  p = tid&63 -> units j0=2p, 2p+1;  q = (tid>>6)&3 -> k-quarter
//                [32q, 32q+32);  rp = tid>>8 -> rows 2rp, 2rp+1.
// Own identity:  jown = tid&127, rown = (tid>>7)&3 -> exactly one h state.
// ---------------------------------------------------------------------------
__global__ void __launch_bounds__(512, 1)
ltc_main(const float* __restrict__ W_r,
         const float* __restrict__ b_r,
         const float* __restrict__ W_fc,
         const float* __restrict__ b_fc,
         float* __restrict__ out)
{
    __shared__ float hs[4][Hsz];            // published hidden state
    __shared__ float part[4][4][Hsz];       // [k-quarter][row][j] partials
    __shared__ float red[4][Hsz];

    const int tid  = threadIdx.x;
    const int p    = tid & 63;
    const int q    = (tid >> 6) & 3;
    const int rp   = tid >> 8;
    const int k0   = q << 5;                // 32*q
    const int j0   = 2 * p;
    const int jown = tid & 127;
    const int rown = (tid >> 7) & 3;
    const int r0   = 2 * rp, r1 = 2 * rp + 1;
    const int base = blockIdx.x * 4;

    // W_r rows j0, j0+1, cols [k0, k0+32): 64 floats in registers.
    ull wA[16], wB[16];
    {
        const ulonglong2* wpA = (const ulonglong2*)(W_r + (size_t)j0 * Hsz + k0);
        const ulonglong2* wpB = (const ulonglong2*)(W_r + (size_t)(j0 + 1) * Hsz + k0);
        #pragma unroll
        for (int c = 0; c < 8; ++c) {
            ulonglong2 vA = wpA[c];
            ulonglong2 vB = wpB[c];
            wA[2 * c] = vA.x;  wA[2 * c + 1] = vA.y;
            wB[2 * c] = vB.x;  wB[2 * c + 1] = vB.y;
        }
    }

    const float bb  = b_r[jown];
    const float wfc = W_fc[jown];

    float h = 0.f;                          // owned state (rown, jown)
    hs[rown][jown] = 0.f;                   // publish initial state

    const size_t xi = (size_t)(base + rown) * Ssz * Hsz + jown;
    float xf = g_xin[xi];

    #pragma unroll 1
    for (int t = 0; t < Ssz; ++t) {
        const float xin = xf + bb;
        if (t + 1 < Ssz)
            xf = g_xin[xi + (size_t)(t + 1) * Hsz];

        #pragma unroll 1
        for (int u = 0; u < UNFOLDS; ++u) {
            __syncthreads();   // h published (and prev partial reads done)

            // dot: 2 units x 2 rows over this thread's k-quarter.
            ull a0 = 0ull, a1 = 0ull, b0 = 0ull, b1 = 0ull;   // row r0
            ull c0 = 0ull, c1 = 0ull, d0 = 0ull, d1 = 0ull;   // row r1
            #pragma unroll     // full unroll: wA/wB must stay in registers
            for (int c = 0; c < 8; ++c) {
                ulonglong2 v0 = *(const ulonglong2*)&hs[r0][k0 + 4 * c];
                ulonglong2 v1 = *(const ulonglong2*)&hs[r1][k0 + 4 * c];
                a0 = ffma2(wA[2 * c], v0.x, a0);  a1 = ffma2(wA[2 * c + 1], v0.y, a1);
                b0 = ffma2(wB[2 * c], v0.x, b0);  b1 = ffma2(wB[2 * c + 1], v0.y, b1);
                c0 = ffma2(wA[2 * c], v1.x, c0);  c1 = ffma2(wA[2 * c + 1], v1.y, c1);
                d0 = ffma2(wB[2 * c], v1.x, d0);  d1 = ffma2(wB[2 * c + 1], v1.y, d1);
            }
            float2 pr0, pr1;
            pr0.x = f2sum(a0) + f2sum(a1);   // (j0,   r0)
            pr0.y = f2sum(b0) + f2sum(b1);   // (j0+1, r0)
            pr1.x = f2sum(c0) + f2sum(c1);   // (j0,   r1)
            pr1.y = f2sum(d0) + f2sum(d1);   // (j0+1, r1)
            *(float2*)&part[q][r0][j0] = pr0;
            *(float2*)&part[q][r1][j0] = pr1;
            __syncthreads();   // partials visible

            // combine 4 quarters + nonlinearity on the single owned state
            const float s = (part[0][rown][jown] + part[1][rown][jown])
                          + (part[2][rown][jown] + part[3][rown][jown]) + xin;
            h = 0.9f * h + 0.1f * ftanh(s);
            hs[rown][jown] = h;
        }
    }

    // out[b] = b_fc + sum_j h[b][j] * W_fc[j]
    __syncthreads();
    red[rown][jown] = h * wfc;
    __syncthreads();

    const int wid = tid >> 5, lane = tid & 31;
    if (wid < 4) {
        float4 v = *(const float4*)&red[wid][4 * lane];
        float s = (v.x + v.y) + (v.z + v.w);
        #pragma unroll
        for (int d = 16; d > 0; d >>= 1)
            s += __shfl_xor_sync(0xffffffffu, s, d);
        if (lane == 0)
            out[base + wid] = s + b_fc[0];
    }
}

extern "C" void kernel_launch(void* const* d_in, const int* in_sizes, int n_in,
                              void* d_out, int out_size)
{
    const float* x    = (const float*)d_in[0];
    const float* W_in = (const float*)d_in[1];
    const float* b_in = (const float*)d_in[2];
    const float* W_r  = (const float*)d_in[3];
    const float* b_r  = (const float*)d_in[4];
    const float* W_fc = (const float*)d_in[5];
    const float* b_fc = (const float*)d_in[6];
    float* out = (float*)d_out;

    xin_kernel<<<(Bsz * Ssz) / 128, 128>>>(x, W_in, b_in);
    ltc_main<<<Bsz / 4, 512>>>(W_r, b_r, W_fc, b_fc, out);
}

// round 9
// speedup vs baseline: 1.2726x; 1.2726x over previous
#include <cuda_runtime.h>
#include <cstdint>

// LTC scan, round 9.
// R8 post-mortem: 16-warp barrier domain + halved per-warp work => overhead
// ratio doubled (regression). Tail structure (2 BAR + partials via shared) is
// the ~470cyc/unfold enemy vs a 512cyc FMA floor.
// R9: CTA=128thr, ROWS=2, grid=256, 2 CTAs/SM (independent 4-warp barrier
// domains that drift). k-half split is INTRA-WARP (hf = lane bit0): partials
// combine via 2x SHFL.XOR(1); h double-buffered => ONE __syncthreads/unfold,
// no shared partial round-trip. +16B pad at k=64 keeps dot LDS.128 reads
// single-wavefront despite the two k-half address streams.

#define Bsz 512
#define Ssz 512
#define Dsz 128
#define Hsz 128
#define UNFOLDS 6
#define HSTRIDE 136   // 128 + 4 (pad at k=64) + 4 (row-stride bank shift)

typedef unsigned long long ull;

__device__ float g_xin[(size_t)Bsz * Ssz * Hsz];   // [b][s][h] scratch

__device__ __forceinline__ ull ffma2(ull a, ull b, ull c) {
    ull d;
    asm("fma.rn.f32x2 %0, %1, %2, %3;" : "=l"(d) : "l"(a), "l"(b), "l"(c));
    return d;
}

__device__ __forceinline__ float f2sum(ull v) {
    float lo, hi;
    asm("mov.b64 {%0, %1}, %2;" : "=f"(lo), "=f"(hi) : "l"(v));
    return lo + hi;
}

__device__ __forceinline__ float ftanh(float s) {
    float e = __expf(2.0f * s);
    return 1.0f - __fdividef(2.0f, e + 1.0f);
}

// ---------------------------------------------------------------------------
// Kernel 1: xin[b,s,j] = sum_d x[b,s,d] * W_in[j,d] + b_in[j]
// ---------------------------------------------------------------------------
__global__ void __launch_bounds__(128, 2)
xin_kernel(const float* __restrict__ x,
           const float* __restrict__ W_in,
           const float* __restrict__ b_in)
{
    __shared__ float xs[2][4 * Dsz];

    const int j = threadIdx.x;

    ull wi[64];
    {
        const ulonglong2* wp = (const ulonglong2*)(W_in + j * Dsz);
        #pragma unroll
        for (int c = 0; c < 32; ++c) {
            ulonglong2 v = wp[c];
            wi[2 * c]     = v.x;
            wi[2 * c + 1] = v.y;
        }
    }
    const float bi = b_in[j];

    const int m0 = blockIdx.x * 128;

    float xf[4];
    #pragma unroll
    for (int r = 0; r < 4; ++r)
        xf[r] = x[(size_t)(m0 + r) * Dsz + j];

    #pragma unroll 1
    for (int ch = 0; ch < 32; ++ch) {
        float* xb = xs[ch & 1];
        #pragma unroll
        for (int r = 0; r < 4; ++r)
            xb[r * Dsz + j] = xf[r];
        __syncthreads();

        if (ch < 31) {
            #pragma unroll
            for (int r = 0; r < 4; ++r)
                xf[r] = x[(size_t)(m0 + (ch + 1) * 4 + r) * Dsz + j];
        }

        ull a0 = 0ull, a1 = 0ull, a2 = 0ull, a3 = 0ull;
        ull a4 = 0ull, a5 = 0ull, a6 = 0ull, a7 = 0ull;
        #pragma unroll
        for (int c = 0; c < 32; ++c) {
            ulonglong2 v0 = *(const ulonglong2*)(xb + 0 * Dsz + 4 * c);
            ulonglong2 v1 = *(const ulonglong2*)(xb + 1 * Dsz + 4 * c);
            ulonglong2 v2 = *(const ulonglong2*)(xb + 2 * Dsz + 4 * c);
            ulonglong2 v3 = *(const ulonglong2*)(xb + 3 * Dsz + 4 * c);
            a0 = ffma2(wi[2 * c], v0.x, a0);  a1 = ffma2(wi[2 * c + 1], v0.y, a1);
            a2 = ffma2(wi[2 * c], v1.x, a2);  a3 = ffma2(wi[2 * c + 1], v1.y, a3);
            a4 = ffma2(wi[2 * c], v2.x, a4);  a5 = ffma2(wi[2 * c + 1], v2.y, a5);
            a6 = ffma2(wi[2 * c], v3.x, a6);  a7 = ffma2(wi[2 * c + 1], v3.y, a7);
        }
        const int m = m0 + ch * 4;
        g_xin[(size_t)(m + 0) * Hsz + j] = f2sum(a0) + f2sum(a1) + bi;
        g_xin[(size_t)(m + 1) * Hsz + j] = f2sum(a2) + f2sum(a3) + bi;
        g_xin[(size_t)(m + 2) * Hsz + j] = f2sum(a4) + f2sum(a5) + bi;
        g_xin[(size_t)(m + 3) * Hsz + j] = f2sum(a6) + f2sum(a7) + bi;
    }
}

// ---------------------------------------------------------------------------
// Kernel 2: sequential scan. grid 256 x 128 threads, 2 rows/CTA.
// Thread (p = tid>>1, hf = tid&1): dots units j0=2p, 2p+1 over k-half
// [64hf, 64hf+64) for BOTH rows; owns states (j0, row hf), (j0+1, row hf).
// Cross-half combine = SHFL.XOR(1) (partner is same warp). 1 BAR/unfold.
// ---------------------------------------------------------------------------
__global__ void __launch_bounds__(128, 2)
ltc_main(const float* __restrict__ W_r,
         const float* __restrict__ b_r,
         const float* __restrict__ W_fc,
         const float* __restrict__ b_fc,
         float* __restrict__ out)
{
    __shared__ float hs[2][2][HSTRIDE];   // [buf][row][padded k]
    __shared__ float red[2][64];

    const int tid  = threadIdx.x;
    const int p    = tid >> 1;            // j-pair 0..63
    const int hf   = tid & 1;             // k-half AND owned row
    const int j0   = 2 * p;
    const int base = blockIdx.x * 2;
    const int koff = hf * 68;             // 64 floats + 4-float pad at k=64
    const int jph  = j0 + (j0 >= 64 ? 4 : 0);  // padded publish index

    // W_r rows j0, j0+1, cols [64hf, 64hf+64): 128 floats in registers.
    ull wA[32], wB[32];
    {
        const ulonglong2* wpA = (const ulonglong2*)(W_r + (size_t)j0 * Hsz + 64 * hf);
        const ulonglong2* wpB = (const ulonglong2*)(W_r + (size_t)(j0 + 1) * Hsz + 64 * hf);
        #pragma unroll
        for (int c = 0; c < 16; ++c) {
            ulonglong2 vA = wpA[c];
            ulonglong2 vB = wpB[c];
            wA[2 * c] = vA.x;  wA[2 * c + 1] = vA.y;
            wB[2 * c] = vB.x;  wB[2 * c + 1] = vB.y;
        }
    }

    const float2 bb2  = *(const float2*)&b_r[j0];

    float h0 = 0.f, h1 = 0.f;             // (j0, row hf), (j0+1, row hf)

    // Bootstrap: publish h=0 into buffer 0 (each thread covers its row/units).
    hs[0][hf][jph]     = 0.f;
    hs[0][hf][jph + 1] = 0.f;

    const size_t xi = (size_t)(base + hf) * Ssz * Hsz + j0;
    float2 xf = *(const float2*)&g_xin[xi];

    #pragma unroll 1
    for (int t = 0; t < Ssz; ++t) {
        const float xinA = xf.x + bb2.x;
        const float xinB = xf.y + bb2.y;
        if (t + 1 < Ssz)
            xf = *(const float2*)&g_xin[xi + (size_t)(t + 1) * Hsz];

        #pragma unroll 1
        for (int u = 0; u < UNFOLDS; ++u) {
            const float* hb = hs[u & 1][0];        // read buffer
            float*       hn = hs[(u + 1) & 1][0];  // write buffer
            __syncthreads();   // prev publishes visible; write buf != read buf

            // dot: 2 units x 2 rows over this thread's k-half.
            ull a0 = 0ull, a1 = 0ull, b0 = 0ull, b1 = 0ull;   // row 0
            ull c0 = 0ull, c1 = 0ull, d0 = 0ull, d1 = 0ull;   // row 1
            #pragma unroll     // full unroll: wA/wB must stay in registers
            for (int c = 0; c < 16; ++c) {
                ulonglong2 v0 = *(const ulonglong2*)&hb[0 * HSTRIDE + koff + 4 * c];
                ulonglong2 v1 = *(const ulonglong2*)&hb[1 * HSTRIDE + koff + 4 * c];
                a0 = ffma2(wA[2 * c], v0.x, a0);  a1 = ffma2(wA[2 * c + 1], v0.y, a1);
                b0 = ffma2(wB[2 * c], v0.x, b0);  b1 = ffma2(wB[2 * c + 1], v0.y, b1);
                c0 = ffma2(wA[2 * c], v1.x, c0);  c1 = ffma2(wA[2 * c + 1], v1.y, c1);
                d0 = ffma2(wB[2 * c], v1.x, d0);  d1 = ffma2(wB[2 * c + 1], v1.y, d1);
            }
            const float Pa_r0 = f2sum(a0) + f2sum(a1);   // (j0,   row0, my half)
            const float Pb_r0 = f2sum(b0) + f2sum(b1);   // (j0+1, row0, my half)
            const float Pa_r1 = f2sum(c0) + f2sum(c1);   // (j0,   row1, my half)
            const float Pb_r1 = f2sum(d0) + f2sum(d1);   // (j0+1, row1, my half)

            // Exchange with lane^1 (same p, other half, other owned row):
            // send my half of the PARTNER's row; keep my half of MY row.
            const float sendA = hf ? Pa_r0 : Pa_r1;
            const float sendB = hf ? Pb_r0 : Pb_r1;
            const float keepA = hf ? Pa_r1 : Pa_r0;
            const float keepB = hf ? Pb_r1 : Pb_r0;
            const float recvA = __shfl_xor_sync(0xffffffffu, sendA, 1);
            const float recvB = __shfl_xor_sync(0xffffffffu, sendB, 1);

            h0 = 0.9f * h0 + 0.1f * ftanh(keepA + recvA + xinA);
            h1 = 0.9f * h1 + 0.1f * ftanh(keepB + recvB + xinB);

            // publish into next buffer
            float2 st;  st.x = h0;  st.y = h1;
            *(float2*)&hn[hf * HSTRIDE + jph] = st;
        }
    }

    // out[b] = b_fc + sum_j h[b][j] * W_fc[j]
    __syncthreads();
    {
        const float2 wfc2 = *(const float2*)&W_fc[j0];
        red[hf][p] = h0 * wfc2.x + h1 * wfc2.y;
    }
    __syncthreads();

    const int wid = tid >> 5, lane = tid & 31;
    if (wid < 2) {
        float s = red[wid][lane] + red[wid][lane + 32];
        #pragma unroll
        for (int d = 16; d > 0; d >>= 1)
            s += __shfl_xor_sync(0xffffffffu, s, d);
        if (lane == 0)
            out[base + wid] = s + b_fc[0];
    }
}

extern "C" void kernel_launch(void* const* d_in, const int* in_sizes, int n_in,
                              void* d_out, int out_size)
{
    const float* x    = (const float*)d_in[0];
    const float* W_in = (const float*)d_in[1];
    const float* b_in = (const float*)d_in[2];
    const float* W_r  = (const float*)d_in[3];
    const float* b_r  = (const float*)d_in[4];
    const float* W_fc = (const float*)d_in[5];
    const float* b_fc = (const float*)d_in[6];
    float* out = (float*)d_out;

    xin_kernel<<<(Bsz * Ssz) / 128, 128>>>(x, W_in, b_in);
    ltc_main<<<Bsz / 2, 128>>>(W_r, b_r, W_fc, b_fc, out);
}